// round 1
// baseline (speedup 1.0000x reference)
#include <cuda_runtime.h>
#include <math.h>

// ---------------- problem constants ----------------
#define B_    8
#define R_    32
#define C_    128
#define H_    4
#define HD_   32
#define BS_   4
#define SHIFT_ 2
#define G_    8
#define N_    64
#define NW_   512
#define MLP_  512
#define NWIN_TOT (B_ * NW_)           // 4096
#define TOK_TOT  (B_ * R_ * R_ * R_)  // 262144

// ---------------- scratch (static device globals; no allocations) ----------------
__device__ float g_qkv[(size_t)NWIN_TOT * 64 * 384];  // window-order qkv, ~402 MB
__device__ float g_ao [(size_t)TOK_TOT * C_];          // attention output, orig token order, ~134 MB

// =====================================================================
// Kernel 1: gather(roll+box) + LayerNorm + QKV GEMM  (one block per window)
// =====================================================================
__global__ __launch_bounds__(256, 1)
void k1_ln_qkv(const float* __restrict__ inp,
               const float* __restrict__ qkv_w,
               const float* __restrict__ g1,
               const float* __restrict__ b1)
{
    extern __shared__ float sm[];
    float* A  = sm;              // 64 x 132 (padded)
    float* Wt = sm + 64 * 132;   // 128 x 64

    int gw  = blockIdx.x;
    int b   = gw >> 9;
    int win = gw & 511;
    int wx = win >> 6, wy = (win >> 3) & 7, wz = win & 7;

    int tid  = threadIdx.x;
    int lane = tid & 31;
    int wrp  = tid >> 5;

    float4 gg = *(const float4*)(g1 + lane * 4);
    float4 bb = *(const float4*)(b1 + lane * 4);

    // ---- LN for 8 tokens per warp (gathered through roll + box partition) ----
    #pragma unroll
    for (int i = 0; i < 8; i++) {
        int tok = wrp * 8 + i;
        int ix = tok >> 4, iy = (tok >> 2) & 3, iz = tok & 3;
        int X = (wx * 4 + ix + SHIFT_) & 31;
        int Y = (wy * 4 + iy + SHIFT_) & 31;
        int Z = (wz * 4 + iz + SHIFT_) & 31;
        int row = ((b * 32 + X) * 32 + Y) * 32 + Z;
        float4 xv = *(const float4*)(inp + (size_t)row * 128 + lane * 4);
        float s  = xv.x + xv.y + xv.z + xv.w;
        float s2 = xv.x * xv.x + xv.y * xv.y + xv.z * xv.z + xv.w * xv.w;
        #pragma unroll
        for (int o = 16; o > 0; o >>= 1) {
            s  += __shfl_xor_sync(0xffffffffu, s,  o);
            s2 += __shfl_xor_sync(0xffffffffu, s2, o);
        }
        float m   = s * (1.0f / 128.0f);
        float var = fmaxf(s2 * (1.0f / 128.0f) - m * m, 0.0f);
        float inv = rsqrtf(var + 1e-5f);
        float* ar = A + tok * 132 + lane * 4;
        ar[0] = (xv.x - m) * inv * gg.x + bb.x;
        ar[1] = (xv.y - m) * inv * gg.y + bb.y;
        ar[2] = (xv.z - m) * inv * gg.z + bb.z;
        ar[3] = (xv.w - m) * inv * gg.w + bb.w;
    }

    // ---- GEMM: (64 x 128) @ (128 x 384) in 6 column tiles of 64 ----
    int tx = tid & 15;   // cols tx*4
    int ty = tid >> 4;   // rows ty*4

    for (int tile = 0; tile < 6; tile++) {
        __syncthreads();  // A ready (first iter) / Wt free (later iters)
        for (int idx = tid; idx < 128 * 64; idx += 256) {
            int k = idx >> 6, c = idx & 63;
            Wt[idx] = qkv_w[k * 384 + tile * 64 + c];
        }
        __syncthreads();

        float acc[4][4] = {};
        #pragma unroll 4
        for (int k = 0; k < 128; k++) {
            float a0 = A[(ty * 4 + 0) * 132 + k];
            float a1 = A[(ty * 4 + 1) * 132 + k];
            float a2 = A[(ty * 4 + 2) * 132 + k];
            float a3 = A[(ty * 4 + 3) * 132 + k];
            float4 bv = *(float4*)(Wt + k * 64 + tx * 4);
            acc[0][0] += a0 * bv.x; acc[0][1] += a0 * bv.y; acc[0][2] += a0 * bv.z; acc[0][3] += a0 * bv.w;
            acc[1][0] += a1 * bv.x; acc[1][1] += a1 * bv.y; acc[1][2] += a1 * bv.z; acc[1][3] += a1 * bv.w;
            acc[2][0] += a2 * bv.x; acc[2][1] += a2 * bv.y; acc[2][2] += a2 * bv.z; acc[2][3] += a2 * bv.w;
            acc[3][0] += a3 * bv.x; acc[3][1] += a3 * bv.y; acc[3][2] += a3 * bv.z; acc[3][3] += a3 * bv.w;
        }
        #pragma unroll
        for (int i = 0; i < 4; i++) {
            int tok = ty * 4 + i;
            float4 o4 = make_float4(acc[i][0], acc[i][1], acc[i][2], acc[i][3]);
            *(float4*)(g_qkv + ((size_t)(gw * 64 + tok)) * 384 + tile * 64 + tx * 4) = o4;
        }
    }
}

// =====================================================================
// Kernel 2: windowed attention (one block per window; thread = (head,row))
// =====================================================================
__global__ __launch_bounds__(256, 1)
void k2_attn(const float* __restrict__ bias_table)
{
    extern __shared__ float sm[];
    float* Ks = sm;            // 4*64*32
    float* Vs = sm + 8192;     // 4*64*32
    float* bt = sm + 16384;    // 484
    int*   rg = (int*)(sm + 16384 + 484);  // 64

    int gw  = blockIdx.x;
    int b   = gw >> 9;
    int win = gw & 511;
    int wx = win >> 6, wy = (win >> 3) & 7, wz = win & 7;
    int tid = threadIdx.x;

    const float* qkvw = g_qkv + (size_t)gw * 64 * 384;

    // load K and V into smem as [h][c][d]
    for (int i = tid; i < 2048; i += 256) {
        int c  = i >> 5;
        int q4 = i & 31;
        int h  = q4 >> 3;
        int d4 = q4 & 7;
        float4 kv = *(const float4*)(qkvw + c * 384 + 128 + q4 * 4);
        *(float4*)(Ks + ((h * 64 + c) * 32) + d4 * 4) = kv;
        float4 vv = *(const float4*)(qkvw + c * 384 + 256 + q4 * 4);
        *(float4*)(Vs + ((h * 64 + c) * 32) + d4 * 4) = vv;
    }
    for (int i = tid; i < 484; i += 256) bt[i] = bias_table[i];
    if (tid < 64) {
        int ix = tid >> 4, iy = (tid >> 2) & 3, iz = tid & 3;
        int X = wx * 4 + ix, Y = wy * 4 + iy, Z = wz * 4 + iz;
        int cx = (X < 28) ? 0 : ((X < 30) ? 1 : 2);
        int cy = (Y < 28) ? 0 : ((Y < 30) ? 1 : 2);
        int cz = (Z < 28) ? 0 : ((Z < 30) ? 1 : 2);
        rg[tid] = 9 * cx + 3 * cy + cz;
    }
    __syncthreads();

    int h = tid >> 6;
    int r = tid & 63;
    int ix = r >> 4, iy = (r >> 2) & 3, iz = r & 3;
    int abase = 11 * ix + iy + iz + 39;
    int myrg  = rg[r];

    // q row in registers (scaled by HD^-0.5)
    float q[32];
    {
        const float* qp = qkvw + r * 384 + h * 32;
        const float scale = 0.17677669529663687f;
        #pragma unroll
        for (int d4 = 0; d4 < 8; d4++) {
            float4 t = *(const float4*)(qp + d4 * 4);
            q[d4 * 4 + 0] = t.x * scale;
            q[d4 * 4 + 1] = t.y * scale;
            q[d4 * 4 + 2] = t.z * scale;
            q[d4 * 4 + 3] = t.w * scale;
        }
    }

    // scores + bias + mask, tracking max
    float p[64];
    float mx = -1e30f;
    const float* Kh = Ks + h * 64 * 32;
    #pragma unroll
    for (int c = 0; c < 64; c++) {
        float s = 0.0f;
        const float* kr = Kh + c * 32;
        #pragma unroll
        for (int d4 = 0; d4 < 8; d4++) {
            float4 t = *(const float4*)(kr + d4 * 4);
            s += q[d4 * 4 + 0] * t.x + q[d4 * 4 + 1] * t.y
               + q[d4 * 4 + 2] * t.z + q[d4 * 4 + 3] * t.w;
        }
        int jx = c >> 4, jy = (c >> 2) & 3, jz = c & 3;
        int idx = abase - (11 * jx + jy + jz);
        s += bt[idx * 4 + h];
        if (rg[c] != myrg) s -= 100.0f;
        p[c] = s;
        mx = fmaxf(mx, s);
    }

    // softmax
    float sum = 0.0f;
    #pragma unroll
    for (int c = 0; c < 64; c++) { p[c] = __expf(p[c] - mx); sum += p[c]; }
    float inv = 1.0f / sum;

    // attn @ V
    float o[32] = {};
    const float* Vh = Vs + h * 64 * 32;
    #pragma unroll
    for (int c = 0; c < 64; c++) {
        float wgt = p[c];
        const float* vr = Vh + c * 32;
        #pragma unroll
        for (int d4 = 0; d4 < 8; d4++) {
            float4 t = *(const float4*)(vr + d4 * 4);
            o[d4 * 4 + 0] += wgt * t.x;
            o[d4 * 4 + 1] += wgt * t.y;
            o[d4 * 4 + 2] += wgt * t.z;
            o[d4 * 4 + 3] += wgt * t.w;
        }
    }

    // write back in ORIGINAL token order (fuses box-reverse + unshift)
    int X = (wx * 4 + ix + SHIFT_) & 31;
    int Y = (wy * 4 + iy + SHIFT_) & 31;
    int Z = (wz * 4 + iz + SHIFT_) & 31;
    int row = ((b * 32 + X) * 32 + Y) * 32 + Z;
    float* op = g_ao + (size_t)row * 128 + h * 32;
    #pragma unroll
    for (int d4 = 0; d4 < 8; d4++) {
        float4 t = make_float4(o[d4 * 4 + 0] * inv, o[d4 * 4 + 1] * inv,
                               o[d4 * 4 + 2] * inv, o[d4 * 4 + 3] * inv);
        *(float4*)(op + d4 * 4) = t;
    }
}

// =====================================================================
// Kernel 3: proj + residual + LN2 + MLP(GELU) + residual (32 tokens/block)
// =====================================================================
__device__ __forceinline__ float gelu_exact(float v)
{
    return 0.5f * v * (1.0f + erff(v * 0.70710678118654752f));
}

__global__ __launch_bounds__(256, 1)
void k3_proj_mlp(const float* __restrict__ inp,
                 const float* __restrict__ proj_w,
                 const float* __restrict__ proj_b,
                 const float* __restrict__ g2,
                 const float* __restrict__ b2,
                 const float* __restrict__ w1,
                 const float* __restrict__ bb1,
                 const float* __restrict__ w2,
                 const float* __restrict__ bb2,
                 float* __restrict__ out)
{
    extern __shared__ float sm[];
    float* AO = sm;                     // 32 x 132 (also reused as H after LN2)
    float* Xs = sm + 4224;              // 32 x 132
    float* H1 = sm + 8448;              // 32 x 516
    float* Wt = sm + 8448 + 16512;      // 128 x 128

    size_t t0 = (size_t)blockIdx.x * 32;
    int tid = threadIdx.x;

    // load attention output rows (contiguous: k2 wrote orig order)
    for (int i = tid; i < 32 * 32; i += 256) {
        int r = i >> 5, c4 = i & 31;
        float4 t = *(const float4*)(g_ao + (t0 + r) * 128 + c4 * 4);
        *(float4*)(AO + r * 132 + c4 * 4) = t;
    }
    for (int i = tid; i < 16384; i += 256) Wt[i] = proj_w[i];
    __syncthreads();

    // ---- proj: (32x128) @ (128x128), +bias, *0.5, +input residual -> Xs ----
    {
        int tx = tid & 31;   // cols tx*4
        int ty = tid >> 5;   // rows ty*4
        float acc[4][4] = {};
        #pragma unroll 4
        for (int k = 0; k < 128; k++) {
            float a0 = AO[(ty * 4 + 0) * 132 + k];
            float a1 = AO[(ty * 4 + 1) * 132 + k];
            float a2 = AO[(ty * 4 + 2) * 132 + k];
            float a3 = AO[(ty * 4 + 3) * 132 + k];
            float4 bv = *(float4*)(Wt + k * 128 + tx * 4);
            acc[0][0] += a0 * bv.x; acc[0][1] += a0 * bv.y; acc[0][2] += a0 * bv.z; acc[0][3] += a0 * bv.w;
            acc[1][0] += a1 * bv.x; acc[1][1] += a1 * bv.y; acc[1][2] += a1 * bv.z; acc[1][3] += a1 * bv.w;
            acc[2][0] += a2 * bv.x; acc[2][1] += a2 * bv.y; acc[2][2] += a2 * bv.z; acc[2][3] += a2 * bv.w;
            acc[3][0] += a3 * bv.x; acc[3][1] += a3 * bv.y; acc[3][2] += a3 * bv.z; acc[3][3] += a3 * bv.w;
        }
        float4 pb = *(const float4*)(proj_b + tx * 4);
        #pragma unroll
        for (int i = 0; i < 4; i++) {
            int r = ty * 4 + i;
            float4 xin = *(const float4*)(inp + (t0 + r) * 128 + tx * 4);
            float4 xv;
            xv.x = (acc[i][0] + pb.x) * 0.5f + xin.x;
            xv.y = (acc[i][1] + pb.y) * 0.5f + xin.y;
            xv.z = (acc[i][2] + pb.z) * 0.5f + xin.z;
            xv.w = (acc[i][3] + pb.w) * 0.5f + xin.w;
            *(float4*)(Xs + r * 132 + tx * 4) = xv;
        }
    }
    __syncthreads();

    // ---- LN2: H (in AO buffer) = LN(Xs) ----
    {
        int r   = tid >> 3;
        int sub = tid & 7;
        float s = 0.0f, s2 = 0.0f;
        for (int c = sub; c < 128; c += 8) {
            float v = Xs[r * 132 + c];
            s += v; s2 += v * v;
        }
        #pragma unroll
        for (int o = 4; o > 0; o >>= 1) {
            s  += __shfl_xor_sync(0xffffffffu, s,  o);
            s2 += __shfl_xor_sync(0xffffffffu, s2, o);
        }
        float m   = s * (1.0f / 128.0f);
        float var = fmaxf(s2 * (1.0f / 128.0f) - m * m, 0.0f);
        float invd = rsqrtf(var + 1e-5f);
        for (int c = sub; c < 128; c += 8) {
            AO[r * 132 + c] = (Xs[r * 132 + c] - m) * invd * g2[c] + b2[c];
        }
    }
    __syncthreads();

    // ---- MLP1: H1 = gelu(H @ w1 + bb1), 8 column tiles of 64 ----
    {
        int tx = tid & 15;   // cols tx*4
        int ty = tid >> 4;   // rows ty*2
        for (int tile = 0; tile < 8; tile++) {
            __syncthreads();
            for (int i = tid; i < 8192; i += 256) {
                int k = i >> 6, c = i & 63;
                Wt[i] = w1[k * 512 + tile * 64 + c];
            }
            __syncthreads();
            float acc[2][4] = {};
            #pragma unroll 4
            for (int k = 0; k < 128; k++) {
                float a0 = AO[(ty * 2 + 0) * 132 + k];
                float a1 = AO[(ty * 2 + 1) * 132 + k];
                float4 bv = *(float4*)(Wt + k * 64 + tx * 4);
                acc[0][0] += a0 * bv.x; acc[0][1] += a0 * bv.y; acc[0][2] += a0 * bv.z; acc[0][3] += a0 * bv.w;
                acc[1][0] += a1 * bv.x; acc[1][1] += a1 * bv.y; acc[1][2] += a1 * bv.z; acc[1][3] += a1 * bv.w;
            }
            float4 b1v = *(const float4*)(bb1 + tile * 64 + tx * 4);
            #pragma unroll
            for (int i = 0; i < 2; i++) {
                int r = ty * 2 + i;
                float4 gv;
                gv.x = gelu_exact(acc[i][0] + b1v.x);
                gv.y = gelu_exact(acc[i][1] + b1v.y);
                gv.z = gelu_exact(acc[i][2] + b1v.z);
                gv.w = gelu_exact(acc[i][3] + b1v.w);
                *(float4*)(H1 + r * 516 + tile * 64 + tx * 4) = gv;
            }
        }
    }

    // ---- MLP2: out = (H1 @ w2 + bb2) * 0.5 + Xs ----
    {
        int tx = tid & 15;   // cols tx*4 within 64-col tile
        int ty = tid >> 4;   // rows ty*2
        for (int ct = 0; ct < 2; ct++) {
            float acc[2][4] = {};
            for (int kc = 0; kc < 4; kc++) {
                __syncthreads();
                for (int i = tid; i < 8192; i += 256) {
                    int k = i >> 6, c = i & 63;
                    Wt[i] = w2[(kc * 128 + k) * 128 + ct * 64 + c];
                }
                __syncthreads();
                #pragma unroll 4
                for (int k = 0; k < 128; k++) {
                    float a0 = H1[(ty * 2 + 0) * 516 + kc * 128 + k];
                    float a1 = H1[(ty * 2 + 1) * 516 + kc * 128 + k];
                    float4 bv = *(float4*)(Wt + k * 64 + tx * 4);
                    acc[0][0] += a0 * bv.x; acc[0][1] += a0 * bv.y; acc[0][2] += a0 * bv.z; acc[0][3] += a0 * bv.w;
                    acc[1][0] += a1 * bv.x; acc[1][1] += a1 * bv.y; acc[1][2] += a1 * bv.z; acc[1][3] += a1 * bv.w;
                }
            }
            float4 b2v = *(const float4*)(bb2 + ct * 64 + tx * 4);
            #pragma unroll
            for (int i = 0; i < 2; i++) {
                int r = ty * 2 + i;
                float4 ov;
                ov.x = (acc[i][0] + b2v.x) * 0.5f + Xs[r * 132 + ct * 64 + tx * 4 + 0];
                ov.y = (acc[i][1] + b2v.y) * 0.5f + Xs[r * 132 + ct * 64 + tx * 4 + 1];
                ov.z = (acc[i][2] + b2v.z) * 0.5f + Xs[r * 132 + ct * 64 + tx * 4 + 2];
                ov.w = (acc[i][3] + b2v.w) * 0.5f + Xs[r * 132 + ct * 64 + tx * 4 + 3];
                *(float4*)(out + (t0 + r) * 128 + ct * 64 + tx * 4) = ov;
            }
        }
    }
}

// =====================================================================
// launch
// =====================================================================
extern "C" void kernel_launch(void* const* d_in, const int* in_sizes, int n_in,
                              void* d_out, int out_size)
{
    (void)in_sizes; (void)n_in; (void)out_size;
    const float* inputs     = (const float*)d_in[0];
    const float* qkv_w      = (const float*)d_in[1];
    const float* proj_w     = (const float*)d_in[2];
    const float* proj_b     = (const float*)d_in[3];
    const float* bias_table = (const float*)d_in[4];
    const float* g1         = (const float*)d_in[5];
    const float* b1         = (const float*)d_in[6];
    const float* g2         = (const float*)d_in[7];
    const float* b2         = (const float*)d_in[8];
    const float* w1         = (const float*)d_in[9];
    const float* bb1        = (const float*)d_in[10];
    const float* w2         = (const float*)d_in[11];
    const float* bb2        = (const float*)d_in[12];
    float* out = (float*)d_out;

    size_t sm1 = (size_t)(64 * 132 + 128 * 64) * 4;                    // 66,560 B
    size_t sm2 = (size_t)(8192 + 8192 + 484 + 64) * 4;                 // 67,728 B
    size_t sm3 = (size_t)(4224 + 4224 + 16512 + 16384) * 4;            // 165,376 B

    cudaFuncSetAttribute(k1_ln_qkv,   cudaFuncAttributeMaxDynamicSharedMemorySize, (int)sm1);
    cudaFuncSetAttribute(k2_attn,     cudaFuncAttributeMaxDynamicSharedMemorySize, (int)sm2);
    cudaFuncSetAttribute(k3_proj_mlp, cudaFuncAttributeMaxDynamicSharedMemorySize, (int)sm3);

    k1_ln_qkv<<<NWIN_TOT, 256, sm1>>>(inputs, qkv_w, g1, b1);
    k2_attn<<<NWIN_TOT, 256, sm2>>>(bias_table);
    k3_proj_mlp<<<TOK_TOT / 32, 256, sm3>>>(inputs, proj_w, proj_b, g2, b2,
                                            w1, bb1, w2, bb2, out);
}

// round 2
// speedup vs baseline: 2.8285x; 2.8285x over previous
#include <cuda_runtime.h>
#include <mma.h>
#include <math.h>

using namespace nvcuda;

// ---------------- problem constants ----------------
#define B_    8
#define R_    32
#define C_    128
#define H_    4
#define HD_   32
#define BS_   4
#define SHIFT_ 2
#define G_    8
#define N_    64
#define NW_   512
#define MLP_  512
#define NWIN_TOT (B_ * NW_)           // 4096
#define TOK_TOT  (B_ * R_ * R_ * R_)  // 262144

// ---------------- scratch ----------------
__device__ float g_ln [(size_t)TOK_TOT * 128];   // LN output (window order for LN1, orig order for LN2)
__device__ float g_qkv[(size_t)TOK_TOT * 384];   // qkv, window order
__device__ float g_ao [(size_t)TOK_TOT * 128];   // attention out, orig order
__device__ float g_x  [(size_t)TOK_TOT * 128];   // residual stream after proj
__device__ float g_h1 [(size_t)TOK_TOT * 512];   // gelu(mlp1)

__device__ __forceinline__ float t32(float x) { return wmma::__float_to_tf32(x); }

template<typename F>
__device__ __forceinline__ void cvt_frag(F& f) {
    #pragma unroll
    for (int t = 0; t < f.num_elements; t++) f.x[t] = wmma::__float_to_tf32(f.x[t]);
}

// =====================================================================
// LN1 + gather (roll + box partition) -> g_ln in window order
// =====================================================================
__global__ __launch_bounds__(256, 2)
void ln_gather(const float* __restrict__ inp,
               const float* __restrict__ g1,
               const float* __restrict__ b1)
{
    int gw  = blockIdx.x;
    int b   = gw >> 9;
    int win = gw & 511;
    int wx = win >> 6, wy = (win >> 3) & 7, wz = win & 7;

    int tid  = threadIdx.x;
    int lane = tid & 31;
    int wrp  = tid >> 5;

    float4 gg = *(const float4*)(g1 + lane * 4);
    float4 bb = *(const float4*)(b1 + lane * 4);

    #pragma unroll
    for (int i = 0; i < 8; i++) {
        int tok = wrp * 8 + i;
        int ix = tok >> 4, iy = (tok >> 2) & 3, iz = tok & 3;
        int X = (wx * 4 + ix + SHIFT_) & 31;
        int Y = (wy * 4 + iy + SHIFT_) & 31;
        int Z = (wz * 4 + iz + SHIFT_) & 31;
        int row = ((b * 32 + X) * 32 + Y) * 32 + Z;
        float4 xv = *(const float4*)(inp + (size_t)row * 128 + lane * 4);
        float s  = xv.x + xv.y + xv.z + xv.w;
        float s2 = xv.x * xv.x + xv.y * xv.y + xv.z * xv.z + xv.w * xv.w;
        #pragma unroll
        for (int o = 16; o > 0; o >>= 1) {
            s  += __shfl_xor_sync(0xffffffffu, s,  o);
            s2 += __shfl_xor_sync(0xffffffffu, s2, o);
        }
        float m   = s * (1.0f / 128.0f);
        float var = fmaxf(s2 * (1.0f / 128.0f) - m * m, 0.0f);
        float inv = rsqrtf(var + 1e-5f);
        float4 o4;
        o4.x = (xv.x - m) * inv * gg.x + bb.x;
        o4.y = (xv.y - m) * inv * gg.y + bb.y;
        o4.z = (xv.z - m) * inv * gg.z + bb.z;
        o4.w = (xv.w - m) * inv * gg.w + bb.w;
        *(float4*)(g_ln + ((size_t)(gw * 64 + tok)) * 128 + lane * 4) = o4;
    }
}

// =====================================================================
// LN2 (plain, orig token order): g_x -> g_ln
// =====================================================================
__global__ __launch_bounds__(256, 4)
void ln_plain(const float* __restrict__ g2,
              const float* __restrict__ b2)
{
    int lane = threadIdx.x & 31;
    int wrp  = threadIdx.x >> 5;
    size_t row = (size_t)blockIdx.x * 8 + wrp;

    float4 gg = *(const float4*)(g2 + lane * 4);
    float4 bb = *(const float4*)(b2 + lane * 4);
    float4 xv = *(const float4*)(g_x + row * 128 + lane * 4);
    float s  = xv.x + xv.y + xv.z + xv.w;
    float s2 = xv.x * xv.x + xv.y * xv.y + xv.z * xv.z + xv.w * xv.w;
    #pragma unroll
    for (int o = 16; o > 0; o >>= 1) {
        s  += __shfl_xor_sync(0xffffffffu, s,  o);
        s2 += __shfl_xor_sync(0xffffffffu, s2, o);
    }
    float m   = s * (1.0f / 128.0f);
    float var = fmaxf(s2 * (1.0f / 128.0f) - m * m, 0.0f);
    float inv = rsqrtf(var + 1e-5f);
    float4 o4;
    o4.x = (xv.x - m) * inv * gg.x + bb.x;
    o4.y = (xv.y - m) * inv * gg.y + bb.y;
    o4.z = (xv.z - m) * inv * gg.z + bb.z;
    o4.w = (xv.w - m) * inv * gg.w + bb.w;
    *(float4*)(g_ln + row * 128 + lane * 4) = o4;
}

// =====================================================================
// Batched tf32 wmma GEMM: C[M,N] = A[M,K] @ W[K,N]  (+ epilogue)
//   EPI 0: plain store
//   EPI 1: (acc + bias[col]) * 0.5 + resid[row*N+col]
//   EPI 2: gelu_exact(acc + bias[col])
// block tile 128x64, 8 warps (4x2), warp tile 32x32, K-chunk 32
// =====================================================================
__device__ __forceinline__ float gelu_exact(float v)
{
    return 0.5f * v * (1.0f + erff(v * 0.70710678118654752f));
}

#define BM 128
#define BN 64
#define BKC 32

template<int EPI>
__global__ __launch_bounds__(256, 2)
void gemm_tf32(const float* __restrict__ A, const float* __restrict__ W,
               float* __restrict__ Cout,
               const float* __restrict__ bias,
               const float* __restrict__ resid,
               int M, int N, int K)
{
    extern __shared__ float sm[];
    float* As = sm;                        // [128][36]
    float* Bs = sm + 128 * 36;             // [32][68]
    float* Cs = sm + 128 * 36 + 32 * 68;   // [128][68]

    int bm = blockIdx.x * BM;
    int bn = blockIdx.y * BN;
    int tid = threadIdx.x;
    int wid = tid >> 5;
    int wm = (wid & 3) * 32;
    int wn = (wid >> 2) * 32;

    wmma::fragment<wmma::accumulator, 16, 16, 8, float> acc[2][2];
    #pragma unroll
    for (int i = 0; i < 2; i++)
        #pragma unroll
        for (int j = 0; j < 2; j++)
            wmma::fill_fragment(acc[i][j], 0.0f);

    for (int k0 = 0; k0 < K; k0 += BKC) {
        // stage A: 128x32 (tf32-rounded)
        #pragma unroll
        for (int i = tid; i < BM * BKC / 4; i += 256) {
            int r  = i >> 3;
            int c4 = (i & 7) * 4;
            float4 v = *(const float4*)(A + (size_t)(bm + r) * K + k0 + c4);
            float* d = As + r * 36 + c4;
            d[0] = t32(v.x); d[1] = t32(v.y); d[2] = t32(v.z); d[3] = t32(v.w);
        }
        // stage B: 32x64 (tf32-rounded)
        #pragma unroll
        for (int i = tid; i < BKC * BN / 4; i += 256) {
            int r  = i >> 4;
            int c4 = (i & 15) * 4;
            float4 v = *(const float4*)(W + (size_t)(k0 + r) * N + bn + c4);
            float* d = Bs + r * 68 + c4;
            d[0] = t32(v.x); d[1] = t32(v.y); d[2] = t32(v.z); d[3] = t32(v.w);
        }
        __syncthreads();

        #pragma unroll
        for (int kk = 0; kk < BKC; kk += 8) {
            wmma::fragment<wmma::matrix_a, 16, 16, 8, wmma::precision::tf32, wmma::row_major> af[2];
            wmma::fragment<wmma::matrix_b, 16, 16, 8, wmma::precision::tf32, wmma::row_major> bf[2];
            #pragma unroll
            for (int i = 0; i < 2; i++)
                wmma::load_matrix_sync(af[i], As + (wm + i * 16) * 36 + kk, 36);
            #pragma unroll
            for (int j = 0; j < 2; j++)
                wmma::load_matrix_sync(bf[j], Bs + kk * 68 + wn + j * 16, 68);
            #pragma unroll
            for (int i = 0; i < 2; i++)
                #pragma unroll
                for (int j = 0; j < 2; j++)
                    wmma::mma_sync(acc[i][j], af[i], bf[j], acc[i][j]);
        }
        __syncthreads();
    }

    // epilogue via smem
    #pragma unroll
    for (int i = 0; i < 2; i++)
        #pragma unroll
        for (int j = 0; j < 2; j++)
            wmma::store_matrix_sync(Cs + (wm + i * 16) * 68 + wn + j * 16, acc[i][j], 68, wmma::mem_row_major);
    __syncthreads();

    #pragma unroll
    for (int i = tid; i < BM * BN / 4; i += 256) {
        int r  = i >> 4;
        int c4 = (i & 15) * 4;
        float* s = Cs + r * 68 + c4;
        size_t row = bm + r;
        int col = bn + c4;
        float4 ov;
        if (EPI == 0) {
            ov = make_float4(s[0], s[1], s[2], s[3]);
        } else if (EPI == 1) {
            float4 bv = *(const float4*)(bias + col);
            float4 rv = *(const float4*)(resid + row * N + col);
            ov.x = (s[0] + bv.x) * 0.5f + rv.x;
            ov.y = (s[1] + bv.y) * 0.5f + rv.y;
            ov.z = (s[2] + bv.z) * 0.5f + rv.z;
            ov.w = (s[3] + bv.w) * 0.5f + rv.w;
        } else {
            float4 bv = *(const float4*)(bias + col);
            ov.x = gelu_exact(s[0] + bv.x);
            ov.y = gelu_exact(s[1] + bv.y);
            ov.z = gelu_exact(s[2] + bv.z);
            ov.w = gelu_exact(s[3] + bv.w);
        }
        *(float4*)(Cout + row * N + col) = ov;
    }
}

// =====================================================================
// Attention with wmma (one block per window; 2 warps per head)
// =====================================================================
__global__ __launch_bounds__(256, 2)
void k2_attn(const float* __restrict__ bias_table)
{
    extern __shared__ float sm[];
    float* Ss = sm;                      // 8 warps x [32][68]
    float* bt = sm + 8 * 32 * 68;        // 484
    int*   rg = (int*)(bt + 484);        // 64

    int gw  = blockIdx.x;
    int b   = gw >> 9;
    int win = gw & 511;
    int wx = win >> 6, wy = (win >> 3) & 7, wz = win & 7;
    int tid  = threadIdx.x;
    int lane = tid & 31;
    int wid  = tid >> 5;

    const float* qkvw = g_qkv + (size_t)gw * 64 * 384;

    for (int i = tid; i < 484; i += 256) bt[i] = bias_table[i];
    if (tid < 64) {
        int ix = tid >> 4, iy = (tid >> 2) & 3, iz = tid & 3;
        int X = wx * 4 + ix, Y = wy * 4 + iy, Z = wz * 4 + iz;
        int cx = (X < 28) ? 0 : ((X < 30) ? 1 : 2);
        int cy = (Y < 28) ? 0 : ((Y < 30) ? 1 : 2);
        int cz = (Z < 28) ? 0 : ((Z < 30) ? 1 : 2);
        rg[tid] = 9 * cx + 3 * cy + cz;
    }
    __syncthreads();

    int h  = wid >> 1;
    int r0 = (wid & 1) * 32;
    float* Sw = Ss + wid * 32 * 68;

    // ---- S = Q @ K^T  (32x64 tile per warp, K=32) ----
    wmma::fragment<wmma::accumulator, 16, 16, 8, float> sacc[2][4];
    #pragma unroll
    for (int i = 0; i < 2; i++)
        #pragma unroll
        for (int j = 0; j < 4; j++)
            wmma::fill_fragment(sacc[i][j], 0.0f);

    const float* Qp = qkvw + (size_t)r0 * 384 + h * 32;   // row-major, ld 384
    const float* Kp = qkvw + 128 + h * 32;                // col-major view (d,m), ld 384
    #pragma unroll
    for (int kk = 0; kk < 32; kk += 8) {
        wmma::fragment<wmma::matrix_a, 16, 16, 8, wmma::precision::tf32, wmma::row_major> af[2];
        wmma::fragment<wmma::matrix_b, 16, 16, 8, wmma::precision::tf32, wmma::col_major> bf[4];
        #pragma unroll
        for (int i = 0; i < 2; i++) {
            wmma::load_matrix_sync(af[i], Qp + (size_t)i * 16 * 384 + kk, 384);
            cvt_frag(af[i]);
        }
        #pragma unroll
        for (int j = 0; j < 4; j++) {
            wmma::load_matrix_sync(bf[j], Kp + (size_t)j * 16 * 384 + kk, 384);
            cvt_frag(bf[j]);
        }
        #pragma unroll
        for (int i = 0; i < 2; i++)
            #pragma unroll
            for (int j = 0; j < 4; j++)
                wmma::mma_sync(sacc[i][j], af[i], bf[j], sacc[i][j]);
    }
    #pragma unroll
    for (int i = 0; i < 2; i++)
        #pragma unroll
        for (int j = 0; j < 4; j++)
            wmma::store_matrix_sync(Sw + i * 16 * 68 + j * 16, sacc[i][j], 68, wmma::mem_row_major);
    __syncwarp();

    // ---- softmax (lane owns row r0+lane) ----
    int rr = r0 + lane;
    int ix = rr >> 4, iy = (rr >> 2) & 3, iz = rr & 3;
    int abase = 11 * ix + iy + iz + 39;
    int myrg  = rg[rr];
    const float scale = 0.17677669529663687f;

    float* prow = Sw + lane * 68;
    float mx = -1e30f;
    #pragma unroll
    for (int c = 0; c < 64; c++) {
        int jx = c >> 4, jy = (c >> 2) & 3, jz = c & 3;
        int idx = abase - (11 * jx + jy + jz);
        float s = prow[c] * scale + bt[idx * 4 + h];
        if (rg[c] != myrg) s -= 100.0f;
        prow[c] = s;
        mx = fmaxf(mx, s);
    }
    float sum = 0.0f;
    #pragma unroll
    for (int c = 0; c < 64; c++) {
        float e = __expf(prow[c] - mx);
        sum += e;
        prow[c] = t32(e);   // pre-round P for tensor op
    }
    float inv = 1.0f / sum;
    __syncwarp();

    // ---- O = P @ V  (32x32, K=64) ----
    wmma::fragment<wmma::accumulator, 16, 16, 8, float> oacc[2][2];
    #pragma unroll
    for (int i = 0; i < 2; i++)
        #pragma unroll
        for (int j = 0; j < 2; j++)
            wmma::fill_fragment(oacc[i][j], 0.0f);

    const float* Vp = qkvw + 256 + h * 32;   // row-major (m,d), ld 384
    #pragma unroll
    for (int kk = 0; kk < 64; kk += 8) {
        wmma::fragment<wmma::matrix_a, 16, 16, 8, wmma::precision::tf32, wmma::row_major> af[2];
        wmma::fragment<wmma::matrix_b, 16, 16, 8, wmma::precision::tf32, wmma::row_major> bf[2];
        #pragma unroll
        for (int i = 0; i < 2; i++)
            wmma::load_matrix_sync(af[i], Sw + i * 16 * 68 + kk, 68);   // already tf32-rounded
        #pragma unroll
        for (int j = 0; j < 2; j++) {
            wmma::load_matrix_sync(bf[j], Vp + (size_t)kk * 384 + j * 16, 384);
            cvt_frag(bf[j]);
        }
        #pragma unroll
        for (int i = 0; i < 2; i++)
            #pragma unroll
            for (int j = 0; j < 2; j++)
                wmma::mma_sync(oacc[i][j], af[i], bf[j], oacc[i][j]);
    }
    __syncwarp();   // all reads of P done before overwrite
    #pragma unroll
    for (int i = 0; i < 2; i++)
        #pragma unroll
        for (int j = 0; j < 2; j++)
            wmma::store_matrix_sync(Sw + i * 16 * 68 + j * 16, oacc[i][j], 68, wmma::mem_row_major);
    __syncwarp();

    // ---- scatter to ORIGINAL token order (fuses box-reverse + unshift) ----
    int X = (wx * 4 + ix + SHIFT_) & 31;
    int Y = (wy * 4 + iy + SHIFT_) & 31;
    int Z = (wz * 4 + iz + SHIFT_) & 31;
    size_t row = ((size_t)(b * 32 + X) * 32 + Y) * 32 + Z;
    float* op = g_ao + row * 128 + h * 32;
    #pragma unroll
    for (int d4 = 0; d4 < 8; d4++) {
        float4 t = *(float4*)(prow + d4 * 4);
        t.x *= inv; t.y *= inv; t.z *= inv; t.w *= inv;
        *(float4*)(op + d4 * 4) = t;
    }
}

// =====================================================================
// launch
// =====================================================================
extern "C" void kernel_launch(void* const* d_in, const int* in_sizes, int n_in,
                              void* d_out, int out_size)
{
    (void)in_sizes; (void)n_in; (void)out_size;
    const float* inputs     = (const float*)d_in[0];
    const float* qkv_w      = (const float*)d_in[1];
    const float* proj_w     = (const float*)d_in[2];
    const float* proj_b     = (const float*)d_in[3];
    const float* bias_table = (const float*)d_in[4];
    const float* g1         = (const float*)d_in[5];
    const float* b1         = (const float*)d_in[6];
    const float* g2         = (const float*)d_in[7];
    const float* b2         = (const float*)d_in[8];
    const float* w1         = (const float*)d_in[9];
    const float* bb1        = (const float*)d_in[10];
    const float* w2         = (const float*)d_in[11];
    const float* bb2        = (const float*)d_in[12];
    float* out = (float*)d_out;

    float* p_ln;  cudaGetSymbolAddress((void**)&p_ln,  g_ln);
    float* p_qkv; cudaGetSymbolAddress((void**)&p_qkv, g_qkv);
    float* p_ao;  cudaGetSymbolAddress((void**)&p_ao,  g_ao);
    float* p_x;   cudaGetSymbolAddress((void**)&p_x,   g_x);
    float* p_h1;  cudaGetSymbolAddress((void**)&p_h1,  g_h1);

    size_t sm_gemm = (size_t)(128 * 36 + 32 * 68 + 128 * 68) * 4;   // 61,952 B
    size_t sm_attn = (size_t)(8 * 32 * 68 + 484 + 64) * 4;          // 71,824 B

    cudaFuncSetAttribute(gemm_tf32<0>, cudaFuncAttributeMaxDynamicSharedMemorySize, (int)sm_gemm);
    cudaFuncSetAttribute(gemm_tf32<1>, cudaFuncAttributeMaxDynamicSharedMemorySize, (int)sm_gemm);
    cudaFuncSetAttribute(gemm_tf32<2>, cudaFuncAttributeMaxDynamicSharedMemorySize, (int)sm_gemm);
    cudaFuncSetAttribute(k2_attn,      cudaFuncAttributeMaxDynamicSharedMemorySize, (int)sm_attn);

    // 1) LN1 + gather
    ln_gather<<<NWIN_TOT, 256>>>(inputs, g1, b1);
    // 2) QKV: (262144 x 128) @ (128 x 384)
    gemm_tf32<0><<<dim3(TOK_TOT / BM, 384 / BN), 256, sm_gemm>>>(
        p_ln, qkv_w, p_qkv, nullptr, nullptr, TOK_TOT, 384, 128);
    // 3) windowed attention -> g_ao (orig order)
    k2_attn<<<NWIN_TOT, 256, sm_attn>>>(bias_table);
    // 4) proj + 0.5x + input residual -> g_x
    gemm_tf32<1><<<dim3(TOK_TOT / BM, 128 / BN), 256, sm_gemm>>>(
        p_ao, proj_w, p_x, proj_b, inputs, TOK_TOT, 128, 128);
    // 5) LN2 -> g_ln
    ln_plain<<<TOK_TOT / 8, 256>>>(g2, b2);
    // 6) MLP1 + gelu -> g_h1
    gemm_tf32<2><<<dim3(TOK_TOT / BM, 512 / BN), 256, sm_gemm>>>(
        p_ln, w1, p_h1, bb1, nullptr, TOK_TOT, 512, 128);
    // 7) MLP2 + 0.5x + residual -> out
    gemm_tf32<1><<<dim3(TOK_TOT / BM, 128 / BN), 256, sm_gemm>>>(
        p_h1, w2, out, bb2, p_x, TOK_TOT, 128, 512);
}

// round 3
// speedup vs baseline: 5.7165x; 2.0210x over previous
#include <cuda_runtime.h>
#include <cuda_bf16.h>
#include <mma.h>
#include <math.h>

using namespace nvcuda;
typedef __nv_bfloat16 bf16;

// ---------------- problem constants ----------------
#define B_    8
#define R_    32
#define SHIFT_ 2
#define TOK_TOT  262144
#define NWIN_TOT 4096

// ---------------- scratch ----------------
__device__ bf16  g_ln [(size_t)TOK_TOT * 128];   // LN out (window order for LN1, orig order for LN2)
__device__ bf16  g_qkv[(size_t)TOK_TOT * 384];   // qkv, window order
__device__ bf16  g_ao [(size_t)TOK_TOT * 128];   // attention out, orig order
__device__ float g_x  [(size_t)TOK_TOT * 128];   // residual stream after proj (fp32)
__device__ bf16  g_h1 [(size_t)TOK_TOT * 512];   // gelu(mlp1)
__device__ bf16  g_wq [128 * 384];
__device__ bf16  g_wp [128 * 128];
__device__ bf16  g_w1 [128 * 512];
__device__ bf16  g_w2 [512 * 128];

__device__ __forceinline__ unsigned pack2(float a, float b) {
    __nv_bfloat162 p;
    p.x = __float2bfloat16(a);
    p.y = __float2bfloat16(b);
    return *(unsigned*)&p;
}

// =====================================================================
// weight conversion (once per launch, trivial)
// =====================================================================
__global__ void cvt_weights(const float* __restrict__ qkv_w, const float* __restrict__ proj_w,
                            const float* __restrict__ w1, const float* __restrict__ w2)
{
    int i = blockIdx.x * 256 + threadIdx.x;
    if (i < 128 * 384) g_wq[i] = __float2bfloat16(qkv_w[i]);
    if (i < 128 * 128) g_wp[i] = __float2bfloat16(proj_w[i]);
    if (i < 128 * 512) g_w1[i] = __float2bfloat16(w1[i]);
    if (i < 512 * 128) g_w2[i] = __float2bfloat16(w2[i]);
}

// =====================================================================
// LN1 + gather (roll + box partition) -> g_ln (bf16, window order)
// =====================================================================
__global__ __launch_bounds__(256, 2)
void ln_gather(const float* __restrict__ inp,
               const float* __restrict__ g1,
               const float* __restrict__ b1)
{
    int gw  = blockIdx.x;
    int b   = gw >> 9;
    int win = gw & 511;
    int wx = win >> 6, wy = (win >> 3) & 7, wz = win & 7;

    int tid  = threadIdx.x;
    int lane = tid & 31;
    int wrp  = tid >> 5;

    float4 gg = *(const float4*)(g1 + lane * 4);
    float4 bb = *(const float4*)(b1 + lane * 4);

    #pragma unroll
    for (int i = 0; i < 8; i++) {
        int tok = wrp * 8 + i;
        int ix = tok >> 4, iy = (tok >> 2) & 3, iz = tok & 3;
        int X = (wx * 4 + ix + SHIFT_) & 31;
        int Y = (wy * 4 + iy + SHIFT_) & 31;
        int Z = (wz * 4 + iz + SHIFT_) & 31;
        int row = ((b * 32 + X) * 32 + Y) * 32 + Z;
        float4 xv = *(const float4*)(inp + (size_t)row * 128 + lane * 4);
        float s  = xv.x + xv.y + xv.z + xv.w;
        float s2 = xv.x * xv.x + xv.y * xv.y + xv.z * xv.z + xv.w * xv.w;
        #pragma unroll
        for (int o = 16; o > 0; o >>= 1) {
            s  += __shfl_xor_sync(0xffffffffu, s,  o);
            s2 += __shfl_xor_sync(0xffffffffu, s2, o);
        }
        float m   = s * (1.0f / 128.0f);
        float var = fmaxf(s2 * (1.0f / 128.0f) - m * m, 0.0f);
        float inv = rsqrtf(var + 1e-5f);
        uint2 u;
        u.x = pack2((xv.x - m) * inv * gg.x + bb.x, (xv.y - m) * inv * gg.y + bb.y);
        u.y = pack2((xv.z - m) * inv * gg.z + bb.z, (xv.w - m) * inv * gg.w + bb.w);
        *(uint2*)(g_ln + ((size_t)(gw * 64 + tok)) * 128 + lane * 4) = u;
    }
}

// =====================================================================
// LN2 (orig token order): g_x (fp32) -> g_ln (bf16)
// =====================================================================
__global__ __launch_bounds__(256, 4)
void ln_plain(const float* __restrict__ g2,
              const float* __restrict__ b2)
{
    int lane = threadIdx.x & 31;
    int wrp  = threadIdx.x >> 5;
    size_t row = (size_t)blockIdx.x * 8 + wrp;

    float4 gg = *(const float4*)(g2 + lane * 4);
    float4 bb = *(const float4*)(b2 + lane * 4);
    float4 xv = *(const float4*)(g_x + row * 128 + lane * 4);
    float s  = xv.x + xv.y + xv.z + xv.w;
    float s2 = xv.x * xv.x + xv.y * xv.y + xv.z * xv.z + xv.w * xv.w;
    #pragma unroll
    for (int o = 16; o > 0; o >>= 1) {
        s  += __shfl_xor_sync(0xffffffffu, s,  o);
        s2 += __shfl_xor_sync(0xffffffffu, s2, o);
    }
    float m   = s * (1.0f / 128.0f);
    float var = fmaxf(s2 * (1.0f / 128.0f) - m * m, 0.0f);
    float inv = rsqrtf(var + 1e-5f);
    uint2 u;
    u.x = pack2((xv.x - m) * inv * gg.x + bb.x, (xv.y - m) * inv * gg.y + bb.y);
    u.y = pack2((xv.z - m) * inv * gg.z + bb.z, (xv.w - m) * inv * gg.w + bb.w);
    *(uint2*)(g_ln + row * 128 + lane * 4) = u;
}

// =====================================================================
// bf16 GEMM: C[M,N] = A[M,K] @ W[K,N] (+ epilogue)
//   A staged ONCE in smem (128 rows x K), N looped in 128-wide tiles,
//   K chunked by 64 with reg->smem double buffering.
//   EPI 0: store bf16
//   EPI 1: (acc + bias[col]) * 0.5 + resid  -> fp32
//   EPI 2: gelu(acc + bias[col])            -> bf16
// =====================================================================
__device__ __forceinline__ float gelu_exact(float v)
{
    return 0.5f * v * (1.0f + erff(v * 0.70710678118654752f));
}

template<int EPI, int KDIM>
__global__ __launch_bounds__(256, 2)
void gemm_bf16(const bf16* __restrict__ A, const bf16* __restrict__ W,
               void* __restrict__ Cout,
               const float* __restrict__ bias,
               const float* __restrict__ resid, int N)
{
    constexpr int LDA = KDIM + 8;
    extern __shared__ char smraw[];
    bf16*  As = (bf16*)smraw;               // [128][LDA]
    bf16*  Ws = As + 128 * LDA;             // [2][64][136]
    float* Cs = (float*)(Ws + 2 * 64 * 136);// [128][68]

    int bm  = blockIdx.x * 128;
    int tid = threadIdx.x;
    int wid = tid >> 5;
    int wm  = (wid & 3) * 32;
    int wn  = (wid >> 2) * 64;

    // stage A once (bf16, 8 elems per float4)
    #pragma unroll 4
    for (int i = tid; i < 128 * KDIM / 8; i += 256) {
        int r  = i / (KDIM / 8);
        int c8 = (i % (KDIM / 8)) * 8;
        float4 v = *(const float4*)(A + (size_t)(bm + r) * KDIM + c8);
        *(float4*)(As + r * LDA + c8) = v;
    }

    const int NT = N >> 7;
    for (int nt = 0; nt < NT; nt++) {
        int bn = nt << 7;
        constexpr int NC = KDIM / 64;

        // prologue: stage W chunk 0
        #pragma unroll
        for (int u = 0; u < 4; u++) {
            int i = tid + u * 256;
            int r = i >> 4, c8 = (i & 15) * 8;
            *(float4*)(Ws + r * 136 + c8) = *(const float4*)(W + (size_t)r * N + bn + c8);
        }
        __syncthreads();

        wmma::fragment<wmma::accumulator, 16, 16, 16, float> acc[2][4];
        #pragma unroll
        for (int i = 0; i < 2; i++)
            #pragma unroll
            for (int j = 0; j < 4; j++)
                wmma::fill_fragment(acc[i][j], 0.0f);

        for (int c = 0; c < NC; c++) {
            float4 wreg[4];
            if (c + 1 < NC) {
                const bf16* src = W + (size_t)((c + 1) * 64) * N + bn;
                #pragma unroll
                for (int u = 0; u < 4; u++) {
                    int i = tid + u * 256;
                    int r = i >> 4, c8 = (i & 15) * 8;
                    wreg[u] = *(const float4*)(src + (size_t)r * N + c8);
                }
            }
            const bf16* Wb = Ws + (c & 1) * 64 * 136;
            #pragma unroll
            for (int kk = 0; kk < 64; kk += 16) {
                wmma::fragment<wmma::matrix_a, 16, 16, 16, bf16, wmma::row_major> af[2];
                wmma::fragment<wmma::matrix_b, 16, 16, 16, bf16, wmma::row_major> bfr[4];
                #pragma unroll
                for (int i = 0; i < 2; i++)
                    wmma::load_matrix_sync(af[i], As + (wm + i * 16) * LDA + c * 64 + kk, LDA);
                #pragma unroll
                for (int j = 0; j < 4; j++)
                    wmma::load_matrix_sync(bfr[j], Wb + kk * 136 + wn + j * 16, 136);
                #pragma unroll
                for (int i = 0; i < 2; i++)
                    #pragma unroll
                    for (int j = 0; j < 4; j++)
                        wmma::mma_sync(acc[i][j], af[i], bfr[j], acc[i][j]);
            }
            if (c + 1 < NC) {
                bf16* dst = Ws + ((c + 1) & 1) * 64 * 136;
                #pragma unroll
                for (int u = 0; u < 4; u++) {
                    int i = tid + u * 256;
                    int r = i >> 4, c8 = (i & 15) * 8;
                    *(float4*)(dst + r * 136 + c8) = wreg[u];
                }
            }
            __syncthreads();
        }

        // epilogue: two passes of 64 columns through Cs
        #pragma unroll
        for (int p = 0; p < 2; p++) {
            if ((wid >> 2) == p) {
                #pragma unroll
                for (int i = 0; i < 2; i++)
                    #pragma unroll
                    for (int j = 0; j < 4; j++)
                        wmma::store_matrix_sync(Cs + (wm + i * 16) * 68 + j * 16, acc[i][j], 68, wmma::mem_row_major);
            }
            __syncthreads();
            #pragma unroll 4
            for (int i = tid; i < 128 * 64 / 4; i += 256) {
                int r  = i >> 4;
                int c4 = (i & 15) * 4;
                float* s = Cs + r * 68 + c4;
                size_t row = bm + r;
                int col = bn + p * 64 + c4;
                if (EPI == 0) {
                    uint2 u;
                    u.x = pack2(s[0], s[1]);
                    u.y = pack2(s[2], s[3]);
                    *(uint2*)((bf16*)Cout + row * N + col) = u;
                } else if (EPI == 1) {
                    float4 bv = *(const float4*)(bias + col);
                    float4 rv = *(const float4*)(resid + row * N + col);
                    float4 ov;
                    ov.x = (s[0] + bv.x) * 0.5f + rv.x;
                    ov.y = (s[1] + bv.y) * 0.5f + rv.y;
                    ov.z = (s[2] + bv.z) * 0.5f + rv.z;
                    ov.w = (s[3] + bv.w) * 0.5f + rv.w;
                    *(float4*)((float*)Cout + row * N + col) = ov;
                } else {
                    float4 bv = *(const float4*)(bias + col);
                    uint2 u;
                    u.x = pack2(gelu_exact(s[0] + bv.x), gelu_exact(s[1] + bv.y));
                    u.y = pack2(gelu_exact(s[2] + bv.z), gelu_exact(s[3] + bv.w));
                    *(uint2*)((bf16*)Cout + row * N + col) = u;
                }
            }
            __syncthreads();
        }
    }
}

// =====================================================================
// Attention (bf16 MMA; one block per window; 2 warps per head)
// =====================================================================
__global__ __launch_bounds__(256, 2)
void attn_bf16(const float* __restrict__ bias_table)
{
    extern __shared__ char smraw[];
    float* Ss = (float*)smraw;                 // 8 x [32][68] fp32
    bf16*  Pb = (bf16*)(Ss + 8 * 32 * 68);     // 8 x [32][72] bf16
    float* bt = (float*)(Pb + 8 * 32 * 72);    // 484
    int*   rg = (int*)(bt + 484);              // 64

    int gw  = blockIdx.x;
    int b   = gw >> 9;
    int win = gw & 511;
    int wx = win >> 6, wy = (win >> 3) & 7, wz = win & 7;
    int tid  = threadIdx.x;
    int lane = tid & 31;
    int wid  = tid >> 5;

    const bf16* qkvw = g_qkv + (size_t)gw * 64 * 384;

    for (int i = tid; i < 484; i += 256) bt[i] = bias_table[i];
    if (tid < 64) {
        int ix = tid >> 4, iy = (tid >> 2) & 3, iz = tid & 3;
        int X = wx * 4 + ix, Y = wy * 4 + iy, Z = wz * 4 + iz;
        int cx = (X < 28) ? 0 : ((X < 30) ? 1 : 2);
        int cy = (Y < 28) ? 0 : ((Y < 30) ? 1 : 2);
        int cz = (Z < 28) ? 0 : ((Z < 30) ? 1 : 2);
        rg[tid] = 9 * cx + 3 * cy + cz;
    }
    __syncthreads();

    int h  = wid >> 1;
    int r0 = (wid & 1) * 32;
    float* Sw = Ss + wid * 32 * 68;
    bf16*  Pw = Pb + wid * 32 * 72;

    // ---- S = Q @ K^T (32x64 per warp, K=32) ----
    wmma::fragment<wmma::accumulator, 16, 16, 16, float> sacc[2][4];
    #pragma unroll
    for (int i = 0; i < 2; i++)
        #pragma unroll
        for (int j = 0; j < 4; j++)
            wmma::fill_fragment(sacc[i][j], 0.0f);

    const bf16* Qp = qkvw + (size_t)r0 * 384 + h * 32;
    const bf16* Kp = qkvw + 128 + h * 32;
    #pragma unroll
    for (int kk = 0; kk < 32; kk += 16) {
        wmma::fragment<wmma::matrix_a, 16, 16, 16, bf16, wmma::row_major> af[2];
        wmma::fragment<wmma::matrix_b, 16, 16, 16, bf16, wmma::col_major> bfr[4];
        #pragma unroll
        for (int i = 0; i < 2; i++)
            wmma::load_matrix_sync(af[i], Qp + (size_t)i * 16 * 384 + kk, 384);
        #pragma unroll
        for (int j = 0; j < 4; j++)
            wmma::load_matrix_sync(bfr[j], Kp + (size_t)j * 16 * 384 + kk, 384);
        #pragma unroll
        for (int i = 0; i < 2; i++)
            #pragma unroll
            for (int j = 0; j < 4; j++)
                wmma::mma_sync(sacc[i][j], af[i], bfr[j], sacc[i][j]);
    }
    #pragma unroll
    for (int i = 0; i < 2; i++)
        #pragma unroll
        for (int j = 0; j < 4; j++)
            wmma::store_matrix_sync(Sw + i * 16 * 68 + j * 16, sacc[i][j], 68, wmma::mem_row_major);
    __syncwarp();

    // ---- softmax (lane owns row r0+lane) ----
    int rr = r0 + lane;
    int ix = rr >> 4, iy = (rr >> 2) & 3, iz = rr & 3;
    int abase = 11 * ix + iy + iz + 39;
    int myrg  = rg[rr];
    const float scale = 0.17677669529663687f;

    float* prow = Sw + lane * 68;
    float mx = -1e30f;
    #pragma unroll
    for (int c = 0; c < 64; c++) {
        int jx = c >> 4, jy = (c >> 2) & 3, jz = c & 3;
        int idx = abase - (11 * jx + jy + jz);
        float s = prow[c] * scale + bt[idx * 4 + h];
        if (rg[c] != myrg) s -= 100.0f;
        prow[c] = s;
        mx = fmaxf(mx, s);
    }
    float sum = 0.0f;
    #pragma unroll
    for (int c = 0; c < 64; c++) {
        float e = __expf(prow[c] - mx);
        sum += e;
        Pw[lane * 72 + c] = __float2bfloat16(e);
    }
    float inv = 1.0f / sum;
    __syncwarp();

    // ---- O = P @ V (32x32, K=64) ----
    wmma::fragment<wmma::accumulator, 16, 16, 16, float> oacc[2][2];
    #pragma unroll
    for (int i = 0; i < 2; i++)
        #pragma unroll
        for (int j = 0; j < 2; j++)
            wmma::fill_fragment(oacc[i][j], 0.0f);

    const bf16* Vp = qkvw + 256 + h * 32;
    #pragma unroll
    for (int kk = 0; kk < 64; kk += 16) {
        wmma::fragment<wmma::matrix_a, 16, 16, 16, bf16, wmma::row_major> af[2];
        wmma::fragment<wmma::matrix_b, 16, 16, 16, bf16, wmma::row_major> bfr[2];
        #pragma unroll
        for (int i = 0; i < 2; i++)
            wmma::load_matrix_sync(af[i], Pw + i * 16 * 72 + kk, 72);
        #pragma unroll
        for (int j = 0; j < 2; j++)
            wmma::load_matrix_sync(bfr[j], Vp + (size_t)kk * 384 + j * 16, 384);
        #pragma unroll
        for (int i = 0; i < 2; i++)
            #pragma unroll
            for (int j = 0; j < 2; j++)
                wmma::mma_sync(oacc[i][j], af[i], bfr[j], oacc[i][j]);
    }
    __syncwarp();
    #pragma unroll
    for (int i = 0; i < 2; i++)
        #pragma unroll
        for (int j = 0; j < 2; j++)
            wmma::store_matrix_sync(Sw + i * 16 * 68 + j * 16, oacc[i][j], 68, wmma::mem_row_major);
    __syncwarp();

    // ---- scatter to ORIGINAL token order ----
    int X = (wx * 4 + ix + SHIFT_) & 31;
    int Y = (wy * 4 + iy + SHIFT_) & 31;
    int Z = (wz * 4 + iz + SHIFT_) & 31;
    size_t row = ((size_t)(b * 32 + X) * 32 + Y) * 32 + Z;
    bf16* op = g_ao + row * 128 + h * 32;
    float* s = Sw + lane * 68;
    #pragma unroll
    for (int d8 = 0; d8 < 4; d8++) {
        uint4 u;
        u.x = pack2(s[d8 * 8 + 0] * inv, s[d8 * 8 + 1] * inv);
        u.y = pack2(s[d8 * 8 + 2] * inv, s[d8 * 8 + 3] * inv);
        u.z = pack2(s[d8 * 8 + 4] * inv, s[d8 * 8 + 5] * inv);
        u.w = pack2(s[d8 * 8 + 6] * inv, s[d8 * 8 + 7] * inv);
        *(uint4*)(op + d8 * 8) = u;
    }
}

// =====================================================================
// launch
// =====================================================================
extern "C" void kernel_launch(void* const* d_in, const int* in_sizes, int n_in,
                              void* d_out, int out_size)
{
    (void)in_sizes; (void)n_in; (void)out_size;
    const float* inputs     = (const float*)d_in[0];
    const float* qkv_w      = (const float*)d_in[1];
    const float* proj_w     = (const float*)d_in[2];
    const float* proj_b     = (const float*)d_in[3];
    const float* bias_table = (const float*)d_in[4];
    const float* g1         = (const float*)d_in[5];
    const float* b1         = (const float*)d_in[6];
    const float* g2         = (const float*)d_in[7];
    const float* b2         = (const float*)d_in[8];
    const float* w1         = (const float*)d_in[9];
    const float* bb1        = (const float*)d_in[10];
    const float* w2         = (const float*)d_in[11];
    const float* bb2        = (const float*)d_in[12];
    float* out = (float*)d_out;

    bf16 *p_ln, *p_qkv, *p_ao, *p_h1, *p_wq, *p_wp, *p_w1, *p_w2;
    float *p_x;
    cudaGetSymbolAddress((void**)&p_ln,  g_ln);
    cudaGetSymbolAddress((void**)&p_qkv, g_qkv);
    cudaGetSymbolAddress((void**)&p_ao,  g_ao);
    cudaGetSymbolAddress((void**)&p_x,   g_x);
    cudaGetSymbolAddress((void**)&p_h1,  g_h1);
    cudaGetSymbolAddress((void**)&p_wq,  g_wq);
    cudaGetSymbolAddress((void**)&p_wp,  g_wp);
    cudaGetSymbolAddress((void**)&p_w1,  g_w1);
    cudaGetSymbolAddress((void**)&p_w2,  g_w2);

    size_t smK128 = (size_t)128 * 136 * 2 + 2 * 64 * 136 * 2 + 128 * 68 * 4;  // 104,448 B
    size_t smK512 = (size_t)128 * 520 * 2 + 2 * 64 * 136 * 2 + 128 * 68 * 4;  // 202,752 B
    size_t smAttn = (size_t)8 * 32 * 68 * 4 + 8 * 32 * 72 * 2 + 484 * 4 + 64 * 4;  // 108,688 B

    cudaFuncSetAttribute(gemm_bf16<0,128>, cudaFuncAttributeMaxDynamicSharedMemorySize, (int)smK128);
    cudaFuncSetAttribute(gemm_bf16<1,128>, cudaFuncAttributeMaxDynamicSharedMemorySize, (int)smK128);
    cudaFuncSetAttribute(gemm_bf16<2,128>, cudaFuncAttributeMaxDynamicSharedMemorySize, (int)smK128);
    cudaFuncSetAttribute(gemm_bf16<1,512>, cudaFuncAttributeMaxDynamicSharedMemorySize, (int)smK512);
    cudaFuncSetAttribute(attn_bf16,        cudaFuncAttributeMaxDynamicSharedMemorySize, (int)smAttn);

    // 0) weights -> bf16
    cvt_weights<<<256, 256>>>(qkv_w, proj_w, w1, w2);
    // 1) LN1 + gather -> g_ln (window order, bf16)
    ln_gather<<<NWIN_TOT, 256>>>(inputs, g1, b1);
    // 2) QKV: (262144x128) @ (128x384) -> g_qkv bf16
    gemm_bf16<0,128><<<TOK_TOT / 128, 256, smK128>>>(p_ln, p_wq, p_qkv, nullptr, nullptr, 384);
    // 3) windowed attention -> g_ao (orig order, bf16)
    attn_bf16<<<NWIN_TOT, 256, smAttn>>>(bias_table);
    // 4) proj + 0.5x + input residual -> g_x fp32
    gemm_bf16<1,128><<<TOK_TOT / 128, 256, smK128>>>(p_ao, p_wp, p_x, proj_b, inputs, 128);
    // 5) LN2 -> g_ln bf16
    ln_plain<<<TOK_TOT / 8, 256>>>(g2, b2);
    // 6) MLP1 + gelu -> g_h1 bf16
    gemm_bf16<2,128><<<TOK_TOT / 128, 256, smK128>>>(p_ln, p_w1, p_h1, bb1, nullptr, 512);
    // 7) MLP2 + 0.5x + residual -> out fp32
    gemm_bf16<1,512><<<TOK_TOT / 128, 256, smK512>>>(p_h1, p_w2, out, bb2, p_x, 128);
}